// round 4
// baseline (speedup 1.0000x reference)
#include <cuda_runtime.h>
#include <math.h>

#define Bt 8
#define Ct 256
#define Nt 4096

// Scratch (device globals — no allocations allowed)
__device__ float g_h [Bt*Ct*Nt];   // groupnorm output, [B][C][N]
__device__ float g_q [Bt*Nt*Ct];   // [B][N][C], pre-scaled by 1/16
__device__ float g_k [Bt*Nt*Ct];   // [B][N][C]
__device__ float g_v [Bt*Nt*Ct];   // [B][N][C]
__device__ float g_ao[Bt*Nt*Ct];   // attention output, [B][N][C]

// ---------------------------------------------------------------------------
// GroupNorm: one block per (batch, group). 32 groups of 8 channels, N=4096.
// ---------------------------------------------------------------------------
__global__ __launch_bounds__(256) void gn_kernel(const float* __restrict__ x,
                                                 const float* __restrict__ w,
                                                 const float* __restrict__ b) {
    int bg = blockIdx.x;           // 0..255
    int batch = bg >> 5, g = bg & 31;
    const float* xp = x   + ((size_t)(batch*Ct + g*8)) * Nt;
    float*       hp = g_h + ((size_t)(batch*Ct + g*8)) * Nt;
    int tid = threadIdx.x;

    float s = 0.f, ss = 0.f;
    for (int i = tid; i < 8*Nt; i += 256) { float v = xp[i]; s += v; ss += v*v; }

    __shared__ float r1[256], r2[256];
    r1[tid] = s; r2[tid] = ss;
    __syncthreads();
    for (int st = 128; st > 0; st >>= 1) {
        if (tid < st) { r1[tid] += r1[tid+st]; r2[tid] += r2[tid+st]; }
        __syncthreads();
    }
    __shared__ float sc[8], sh[8];
    if (tid < 8) {
        float mean = r1[0] * (1.f/32768.f);
        float var  = r2[0] * (1.f/32768.f) - mean*mean;
        float rstd = rsqrtf(var + 1e-5f);
        float scale = w[g*8 + tid] * rstd;
        sc[tid] = scale;
        sh[tid] = b[g*8 + tid] - mean * scale;
    }
    __syncthreads();
    for (int i = tid; i < 8*Nt; i += 256) {
        int c = i >> 12;
        hp[i] = xp[i] * sc[c] + sh[c];
    }
}

// ---------------------------------------------------------------------------
// QKV projection: out[b][n][o] = scale * (sum_c w[o][c] * h[b][c][n] + bias[o])
// 64 tokens x 64 outs per block, K-chunks of 16. which: 0=Q,1=K,2=V.
// ---------------------------------------------------------------------------
__global__ __launch_bounds__(256) void proj_kernel(const float* __restrict__ w,
                                                   const float* __restrict__ bias,
                                                   int which, float scale) {
    __shared__ float Hs[16*64];
    __shared__ float Ws[64*17];
    int tid = threadIdx.x, tx = tid & 15, ty = tid >> 4;
    int n0 = blockIdx.x * 64, o0 = blockIdx.y * 64, bb = blockIdx.z;
    const float* h = g_h + (size_t)bb * Ct * Nt;
    float* out = (which == 0) ? g_q : (which == 1) ? g_k : g_v;
    out += (size_t)bb * Nt * Ct;

    float acc[4][4] = {};
    for (int kt = 0; kt < 16; kt++) {
        #pragma unroll
        for (int i = 0; i < 4; i++) {
            int e = tid + i*256;
            int k = e >> 6, n = e & 63;
            Hs[e] = h[(size_t)(kt*16 + k)*Nt + n0 + n];
            int r = e >> 4, c = e & 15;
            Ws[r*17 + c] = w[(o0 + r)*Ct + kt*16 + c];
        }
        __syncthreads();
        #pragma unroll
        for (int k = 0; k < 16; k++) {
            float wv[4], hv[4];
            #pragma unroll
            for (int i = 0; i < 4; i++) wv[i] = Ws[(tx*4+i)*17 + k];
            #pragma unroll
            for (int j = 0; j < 4; j++) hv[j] = Hs[k*64 + ty*4 + j];
            #pragma unroll
            for (int i = 0; i < 4; i++)
                #pragma unroll
                for (int j = 0; j < 4; j++) acc[i][j] += wv[i]*hv[j];
        }
        __syncthreads();
    }
    #pragma unroll
    for (int j = 0; j < 4; j++) {
        int n = n0 + ty*4 + j;
        int ob = o0 + tx*4;
        float4 v;
        v.x = (acc[0][j] + bias[ob+0]) * scale;
        v.y = (acc[1][j] + bias[ob+1]) * scale;
        v.z = (acc[2][j] + bias[ob+2]) * scale;
        v.w = (acc[3][j] + bias[ob+3]) * scale;
        *(float4*)&out[(size_t)n*Ct + ob] = v;
    }
}

// ---------------------------------------------------------------------------
// Flash attention: 64 query rows per block, D=256, KV tiles of 64.
// Q stored TRANSPOSED in smem ([c][n]); K chunks (64 c-cols) transposed and
// double-buffered with register prefetch. Inner QK loop uses LDS.128.
// Q pre-scaled by 1/16. Online softmax, O accumulated in registers.
// ---------------------------------------------------------------------------
#define QP 68     // Qs stride  ([256 c][QP]) — mult of 4 for float4 align
#define VP 260    // Vs stride  ([64 m][VP])
#define KP 68     // K chunk stride ([64 c][KP]) — mult of 4
#define PP 65     // Ps stride  ([64 q][PP])
#define FLASH_SMEM_FLOATS (256*QP + 64*VP + 2*64*KP + 64*PP)   // 46912 fl = 187648 B

__global__ __launch_bounds__(256) void flash_kernel() {
    extern __shared__ float sm[];
    float* Qs = sm;                    // [256][68]  transposed Q
    float* Vs = Qs + 256*QP;           // [64][260]
    float* Kb = Vs + 64*VP;            // 2 x [64][68] transposed K chunk
    float* Ps = Kb + 2*64*KP;          // [64][65]

    int tid = threadIdx.x, tx = tid & 15, ty = tid >> 4;
    int n0 = blockIdx.x * 64;
    int bb = blockIdx.y;
    const float* Q = g_q + (size_t)bb * Nt * Ct;
    const float* K = g_k + (size_t)bb * Nt * Ct;
    const float* V = g_v + (size_t)bb * Nt * Ct;

    // Fill Qs transposed: Qs[c][n] = Q[n0+n][c]
    #pragma unroll
    for (int i = 0; i < 16; i++) {
        int e = tid + i*256;
        int n = e & 63, c4 = e >> 6;            // c4: 0..63
        float4 qv = *(const float4*)&Q[(size_t)(n0 + n)*Ct + c4*4];
        Qs[(c4*4+0)*QP + n] = qv.x;
        Qs[(c4*4+1)*QP + n] = qv.y;
        Qs[(c4*4+2)*QP + n] = qv.z;
        Qs[(c4*4+3)*QP + n] = qv.w;
    }

    float m_i[4], l_i[4];
    #pragma unroll
    for (int i = 0; i < 4; i++) { m_i[i] = -1e30f; l_i[i] = 0.f; }
    float o_acc[4][16] = {};

    // Prefetch K chunk (kt=0, dc=0) into registers.
    // Mapping: e = tid + i*256 (i<4), c4 = e>>6 (0..15), m = e&63.
    float4 kreg[4];
    #pragma unroll
    for (int i = 0; i < 4; i++) {
        int e = tid + i*256;
        int c4 = e >> 6, mm = e & 63;
        kreg[i] = *(const float4*)&K[(size_t)mm*Ct + c4*4];
    }

    for (int kt = 0; kt < 64; kt++) {
        __syncthreads();   // prev PV done: Vs/Ps free for overwrite
        // Load V tile [64][256] -> Vs (row-major, stride VP)
        #pragma unroll
        for (int i = 0; i < 16; i++) {
            int e = tid + i*256;
            int mm = e >> 6, c4 = e & 63;
            *(float4*)&Vs[mm*VP + c4*4] =
                *(const float4*)&V[(size_t)(kt*64 + mm)*Ct + c4*4];
        }

        float acc[4][4] = {};
        for (int dc = 0; dc < 4; dc++) {
            float* buf = Kb + (dc & 1) * 64*KP;
            // Store prefetched chunk transposed: buf[c][m]
            #pragma unroll
            for (int i = 0; i < 4; i++) {
                int e = tid + i*256;
                int c4 = e >> 6, mm = e & 63;
                buf[(c4*4+0)*KP + mm] = kreg[i].x;
                buf[(c4*4+1)*KP + mm] = kreg[i].y;
                buf[(c4*4+2)*KP + mm] = kreg[i].z;
                buf[(c4*4+3)*KP + mm] = kreg[i].w;
            }
            __syncthreads();   // chunk visible (ping-pong: no WAR on other buffer)
            // Prefetch next chunk (overlaps with compute below)
            if (dc < 3) {
                #pragma unroll
                for (int i = 0; i < 4; i++) {
                    int e = tid + i*256;
                    int c4 = e >> 6, mm = e & 63;
                    kreg[i] = *(const float4*)&K[(size_t)(kt*64 + mm)*Ct + (dc+1)*64 + c4*4];
                }
            } else if (kt < 63) {
                #pragma unroll
                for (int i = 0; i < 4; i++) {
                    int e = tid + i*256;
                    int c4 = e >> 6, mm = e & 63;
                    kreg[i] = *(const float4*)&K[(size_t)((kt+1)*64 + mm)*Ct + c4*4];
                }
            }
            // Compute: 64 c-columns, vectorized LDS.128
            #pragma unroll 8
            for (int c = 0; c < 64; c++) {
                float4 qv = *(const float4*)&Qs[(dc*64 + c)*QP + ty*4];
                float4 kv = *(const float4*)&buf[c*KP + tx*4];
                acc[0][0] += qv.x*kv.x; acc[0][1] += qv.x*kv.y;
                acc[0][2] += qv.x*kv.z; acc[0][3] += qv.x*kv.w;
                acc[1][0] += qv.y*kv.x; acc[1][1] += qv.y*kv.y;
                acc[1][2] += qv.y*kv.z; acc[1][3] += qv.y*kv.w;
                acc[2][0] += qv.z*kv.x; acc[2][1] += qv.z*kv.y;
                acc[2][2] += qv.z*kv.z; acc[2][3] += qv.z*kv.w;
                acc[3][0] += qv.w*kv.x; acc[3][1] += qv.w*kv.y;
                acc[3][2] += qv.w*kv.z; acc[3][3] += qv.w*kv.w;
            }
            if (dc < 3) __syncthreads();  // compute done before next sts overwrites other buf? (not needed for ping-pong, but protects straggler reading buf while 2-ahead sts lands)
        }

        // Online softmax update (row i = query ty*4+i; reduce across 16 tx lanes)
        float p[4][4];
        #pragma unroll
        for (int i = 0; i < 4; i++) {
            float tmax = fmaxf(fmaxf(acc[i][0], acc[i][1]), fmaxf(acc[i][2], acc[i][3]));
            #pragma unroll
            for (int off = 8; off >= 1; off >>= 1)
                tmax = fmaxf(tmax, __shfl_xor_sync(0xffffffffu, tmax, off));
            float mnew  = fmaxf(m_i[i], tmax);
            float alpha = __expf(m_i[i] - mnew);
            float rs = 0.f;
            #pragma unroll
            for (int j = 0; j < 4; j++) { p[i][j] = __expf(acc[i][j] - mnew); rs += p[i][j]; }
            #pragma unroll
            for (int off = 8; off >= 1; off >>= 1)
                rs += __shfl_xor_sync(0xffffffffu, rs, off);
            l_i[i] = alpha * l_i[i] + rs;
            m_i[i] = mnew;
            #pragma unroll
            for (int j = 0; j < 16; j++) o_acc[i][j] *= alpha;
        }
        // Store P tile (row = query, col = key m)
        #pragma unroll
        for (int i = 0; i < 4; i++)
            #pragma unroll
            for (int j = 0; j < 4; j++)
                Ps[(ty*4+i)*PP + tx*4 + j] = p[i][j];
        __syncthreads();
        // P @ V
        #pragma unroll 4
        for (int mm = 0; mm < 64; mm++) {
            float pv[4], vv[16];
            #pragma unroll
            for (int i = 0; i < 4; i++) pv[i] = Ps[(ty*4+i)*PP + mm];
            #pragma unroll
            for (int j = 0; j < 16; j++) vv[j] = Vs[mm*VP + tx + 16*j];
            #pragma unroll
            for (int i = 0; i < 4; i++)
                #pragma unroll
                for (int j = 0; j < 16; j++) o_acc[i][j] += pv[i]*vv[j];
        }
    }

    float* AO = g_ao + (size_t)bb * Nt * Ct;
    #pragma unroll
    for (int i = 0; i < 4; i++) {
        float inv = 1.f / l_i[i];
        #pragma unroll
        for (int j = 0; j < 16; j++)
            AO[(size_t)(n0 + ty*4 + i)*Ct + tx + 16*j] = o_acc[i][j] * inv;
    }
}

// ---------------------------------------------------------------------------
// Output projection + residual: out[b][o][n] = sum_c wo[o][c]*AO[b][n][c] + bo[o] + x[b][o][n]
// ---------------------------------------------------------------------------
__global__ __launch_bounds__(256) void oproj_kernel(const float* __restrict__ w,
                                                    const float* __restrict__ bias,
                                                    const float* __restrict__ x,
                                                    float* __restrict__ out) {
    __shared__ float As[64*17];
    __shared__ float Ws[64*17];
    int tid = threadIdx.x, tx = tid & 15, ty = tid >> 4;
    int n0 = blockIdx.x * 64, o0 = blockIdx.y * 64, bb = blockIdx.z;
    const float* A = g_ao + (size_t)bb * Nt * Ct;

    float acc[4][4] = {};
    for (int kt = 0; kt < 16; kt++) {
        #pragma unroll
        for (int i = 0; i < 4; i++) {
            int e = tid + i*256;
            int r = e >> 4, c = e & 15;
            As[r*17 + c] = A[(size_t)(n0 + r)*Ct + kt*16 + c];
            Ws[r*17 + c] = w[(o0 + r)*Ct + kt*16 + c];
        }
        __syncthreads();
        #pragma unroll
        for (int k = 0; k < 16; k++) {
            float wv[4], av[4];
            #pragma unroll
            for (int i = 0; i < 4; i++) wv[i] = Ws[(ty*4+i)*17 + k];
            #pragma unroll
            for (int j = 0; j < 4; j++) av[j] = As[(tx*4+j)*17 + k];
            #pragma unroll
            for (int i = 0; i < 4; i++)
                #pragma unroll
                for (int j = 0; j < 4; j++) acc[i][j] += wv[i]*av[j];
        }
        __syncthreads();
    }
    #pragma unroll
    for (int i = 0; i < 4; i++) {
        int o = o0 + ty*4 + i;
        size_t base = ((size_t)bb*Ct + o)*Nt + n0 + tx*4;
        float4 xv = *(const float4*)&x[base];
        float bo_ = bias[o];
        float4 ov;
        ov.x = acc[i][0] + bo_ + xv.x;
        ov.y = acc[i][1] + bo_ + xv.y;
        ov.z = acc[i][2] + bo_ + xv.z;
        ov.w = acc[i][3] + bo_ + xv.w;
        *(float4*)&out[base] = ov;
    }
}

// ---------------------------------------------------------------------------
extern "C" void kernel_launch(void* const* d_in, const int* in_sizes, int n_in,
                              void* d_out, int out_size) {
    (void)in_sizes; (void)n_in; (void)out_size;
    const float* x   = (const float*)d_in[0];
    const float* gnw = (const float*)d_in[1];
    const float* gnb = (const float*)d_in[2];
    const float* wq  = (const float*)d_in[3];
    const float* bq  = (const float*)d_in[4];
    const float* wk  = (const float*)d_in[5];
    const float* bk  = (const float*)d_in[6];
    const float* wv  = (const float*)d_in[7];
    const float* bv  = (const float*)d_in[8];
    const float* wo  = (const float*)d_in[9];
    const float* bo  = (const float*)d_in[10];
    float* out = (float*)d_out;

    cudaFuncSetAttribute(flash_kernel, cudaFuncAttributeMaxDynamicSharedMemorySize,
                         FLASH_SMEM_FLOATS * (int)sizeof(float));

    gn_kernel<<<256, 256>>>(x, gnw, gnb);

    dim3 pg(Nt/64, Ct/64, Bt);
    proj_kernel<<<pg, 256>>>(wq, bq, 0, 0.0625f);  // Q, scaled by 1/sqrt(C)
    proj_kernel<<<pg, 256>>>(wk, bk, 1, 1.0f);
    proj_kernel<<<pg, 256>>>(wv, bv, 2, 1.0f);

    dim3 fg(Nt/64, Bt);
    flash_kernel<<<fg, 256, FLASH_SMEM_FLOATS * (int)sizeof(float)>>>();

    oproj_kernel<<<pg, 256>>>(wo, bo, x, out);
}

// round 8
// speedup vs baseline: 6.2310x; 6.2310x over previous
#include <cuda_runtime.h>
#include <cuda_bf16.h>
#include <stdint.h>
#include <math.h>

#define Bt 8
#define Ct 256
#define Nt 4096

// Scratch (device globals — no allocations allowed)
__device__ float         g_h [Bt*Ct*Nt];   // groupnorm output, [B][C][N] fp32
__device__ __nv_bfloat16 g_qb[Bt*Nt*Ct];   // [B][N][C] bf16, pre-scaled 1/16
__device__ __nv_bfloat16 g_kb[Bt*Nt*Ct];   // [B][N][C] bf16
__device__ __nv_bfloat16 g_vb[Bt*Ct*Nt];   // [B][C][N] bf16 (channel-major)
__device__ float         g_ao[Bt*Nt*Ct];   // attention output, [B][N][C] fp32

// ===========================================================================
// sm_80-class tensor-core primitives (legal on base compute_103)
// ===========================================================================
__device__ __forceinline__ uint32_t cvta_smem(const void* p) {
    uint32_t a;
    asm("{ .reg .u64 t; cvta.to.shared.u64 t, %1; cvt.u32.u64 %0, t; }" : "=r"(a) : "l"(p));
    return a;
}
#define LDSM4(r, a) \
    asm volatile("ldmatrix.sync.aligned.m8n8.x4.shared.b16 {%0,%1,%2,%3}, [%4];" \
        : "=r"((r)[0]), "=r"((r)[1]), "=r"((r)[2]), "=r"((r)[3]) : "r"(a))

__device__ __forceinline__ void mma16816(float* d, const uint32_t* a, const uint32_t* b) {
    asm volatile("mma.sync.aligned.m16n8k16.row.col.f32.bf16.bf16.f32 "
        "{%0,%1,%2,%3}, {%4,%5,%6,%7}, {%8,%9}, {%0,%1,%2,%3};"
        : "+f"(d[0]), "+f"(d[1]), "+f"(d[2]), "+f"(d[3])
        : "r"(a[0]), "r"(a[1]), "r"(a[2]), "r"(a[3]), "r"(b[0]), "r"(b[1]));
}
#define CP_ASYNC16(s, g) \
    asm volatile("cp.async.cg.shared.global [%0], [%1], 16;" :: "r"(s), "l"(g))
#define CP_COMMIT()  asm volatile("cp.async.commit_group;")
#define CP_WAIT(N)   asm volatile("cp.async.wait_group %0;" :: "n"(N))

// ---------------------------------------------------------------------------
// GroupNorm
// ---------------------------------------------------------------------------
__global__ __launch_bounds__(256) void gn_kernel(const float* __restrict__ x,
                                                 const float* __restrict__ w,
                                                 const float* __restrict__ b) {
    int bg = blockIdx.x;
    int batch = bg >> 5, g = bg & 31;
    const float* xp = x   + ((size_t)(batch*Ct + g*8)) * Nt;
    float*       hp = g_h + ((size_t)(batch*Ct + g*8)) * Nt;
    int tid = threadIdx.x;

    float s = 0.f, ss = 0.f;
    for (int i = tid; i < 8*Nt; i += 256) { float v = xp[i]; s += v; ss += v*v; }

    __shared__ float r1[256], r2[256];
    r1[tid] = s; r2[tid] = ss;
    __syncthreads();
    for (int st = 128; st > 0; st >>= 1) {
        if (tid < st) { r1[tid] += r1[tid+st]; r2[tid] += r2[tid+st]; }
        __syncthreads();
    }
    __shared__ float sc[8], sh[8];
    if (tid < 8) {
        float mean = r1[0] * (1.f/32768.f);
        float var  = r2[0] * (1.f/32768.f) - mean*mean;
        float rstd = rsqrtf(var + 1e-5f);
        float scale = w[g*8 + tid] * rstd;
        sc[tid] = scale;
        sh[tid] = b[g*8 + tid] - mean * scale;
    }
    __syncthreads();
    for (int i = tid; i < 8*Nt; i += 256) {
        int c = i >> 12;
        hp[i] = xp[i] * sc[c] + sh[c];
    }
}

// ---------------------------------------------------------------------------
// QKV projection -> bf16. which: 0=Q ([N][C], *1/16), 1=K ([N][C]), 2=V ([C][N])
// ---------------------------------------------------------------------------
__global__ __launch_bounds__(256) void proj_kernel(const float* __restrict__ w,
                                                   const float* __restrict__ bias,
                                                   int which, float scale) {
    __shared__ float Hs[16*64];
    __shared__ float Ws[64*17];
    int tid = threadIdx.x, tx = tid & 15, ty = tid >> 4;
    int n0 = blockIdx.x * 64, o0 = blockIdx.y * 64, bb = blockIdx.z;
    const float* h = g_h + (size_t)bb * Ct * Nt;

    float acc[4][4] = {};
    for (int kt = 0; kt < 16; kt++) {
        #pragma unroll
        for (int i = 0; i < 4; i++) {
            int e = tid + i*256;
            int k = e >> 6, n = e & 63;
            Hs[e] = h[(size_t)(kt*16 + k)*Nt + n0 + n];
            int r = e >> 4, c = e & 15;
            Ws[r*17 + c] = w[(o0 + r)*Ct + kt*16 + c];
        }
        __syncthreads();
        #pragma unroll
        for (int k = 0; k < 16; k++) {
            float wv[4], hv[4];
            #pragma unroll
            for (int i = 0; i < 4; i++) wv[i] = Ws[(tx*4+i)*17 + k];
            #pragma unroll
            for (int j = 0; j < 4; j++) hv[j] = Hs[k*64 + ty*4 + j];
            #pragma unroll
            for (int i = 0; i < 4; i++)
                #pragma unroll
                for (int j = 0; j < 4; j++) acc[i][j] += wv[i]*hv[j];
        }
        __syncthreads();
    }
    if (which == 2) {
        __nv_bfloat16* out = g_vb + (size_t)bb * Ct * Nt;
        #pragma unroll
        for (int i = 0; i < 4; i++) {
            int o = o0 + tx*4 + i;
            float bo_ = bias[o];
            __nv_bfloat162 p0 = __floats2bfloat162_rn(acc[i][0]+bo_, acc[i][1]+bo_);
            __nv_bfloat162 p1 = __floats2bfloat162_rn(acc[i][2]+bo_, acc[i][3]+bo_);
            uint2 u; u.x = *(uint32_t*)&p0; u.y = *(uint32_t*)&p1;
            *(uint2*)&out[(size_t)o*Nt + n0 + ty*4] = u;
        }
    } else {
        __nv_bfloat16* out = (which == 0) ? g_qb : g_kb;
        out += (size_t)bb * Nt * Ct;
        #pragma unroll
        for (int j = 0; j < 4; j++) {
            int n = n0 + ty*4 + j;
            int ob = o0 + tx*4;
            __nv_bfloat162 p0 = __floats2bfloat162_rn((acc[0][j]+bias[ob+0])*scale, (acc[1][j]+bias[ob+1])*scale);
            __nv_bfloat162 p1 = __floats2bfloat162_rn((acc[2][j]+bias[ob+2])*scale, (acc[3][j]+bias[ob+3])*scale);
            uint2 u; u.x = *(uint32_t*)&p0; u.y = *(uint32_t*)&p1;
            *(uint2*)&out[(size_t)n*Ct + ob] = u;
        }
    }
}

// ---------------------------------------------------------------------------
// Flash attention via mma.sync (bf16, fp32 acc). Br=128 (8 warps x 16 rows),
// Bc=64, D=256. K/V double-buffered via cp.async. Warp owns its rows fully.
// ---------------------------------------------------------------------------
#define QSTR 264                        // bf16 elems per Q smem row (528B)
#define KSTR 264
#define VSTR 72                         // V^T smem: 256 ch rows x 72 (144B)
#define SM_K    (128*QSTR*2)            // Q at 0, size 67584
#define SM_KBUF (64*KSTR*2)             // 33792
#define SM_V    (SM_K + 2*SM_KBUF)      // 135168
#define SM_VBUF (256*VSTR*2)            // 36864
#define FLASH_SMEM (SM_V + 2*SM_VBUF)   // 208896

__device__ __forceinline__ void issue_kv(uint32_t sb,
                                         const __nv_bfloat16* Kp,
                                         const __nv_bfloat16* Vp,
                                         int kt, int buf, int tid) {
    uint32_t kbase = sb + SM_K + buf*SM_KBUF;
    #pragma unroll
    for (int i = 0; i < 8; i++) {
        int e = tid + i*256;
        int r = e >> 5, c8 = e & 31;               // 64 rows x 32 16B-chunks
        CP_ASYNC16(kbase + (uint32_t)(r*KSTR + c8*8)*2,
                   (const void*)&Kp[(size_t)(kt*64 + r)*Ct + c8*8]);
    }
    uint32_t vbase = sb + SM_V + buf*SM_VBUF;
    #pragma unroll
    for (int i = 0; i < 8; i++) {
        int e = tid + i*256;
        int r = e >> 3, c8 = e & 7;                // 256 ch rows x 8 16B-chunks
        CP_ASYNC16(vbase + (uint32_t)(r*VSTR + c8*8)*2,
                   (const void*)&Vp[(size_t)r*Nt + kt*64 + c8*8]);
    }
    CP_COMMIT();
}

__global__ __launch_bounds__(256, 1) void flash_mma() {
    extern __shared__ char smem[];
    const uint32_t sb = cvta_smem(smem);
    const int tid = threadIdx.x, lane = tid & 31, wid = tid >> 5;
    const int g = lane >> 2, tig = lane & 3;
    const int n0 = blockIdx.x * 128, bb = blockIdx.y;
    const __nv_bfloat16* Qp = g_qb + (size_t)bb * Nt * Ct;
    const __nv_bfloat16* Kp = g_kb + (size_t)bb * Nt * Ct;
    const __nv_bfloat16* Vp = g_vb + (size_t)bb * Ct * Nt;

    issue_kv(sb, Kp, Vp, 0, 0, tid);

    // Q tile: 128 rows x 256 ch (LDG.128 -> STS.128)
    #pragma unroll
    for (int i = 0; i < 16; i++) {
        int e = tid + i*256;
        int r = e >> 5, c8 = e & 31;
        uint4 u = *(const uint4*)&Qp[(size_t)(n0 + r)*Ct + c8*8];
        *(uint4*)(smem + (size_t)(r*QSTR + c8*8)*2) = u;
    }

    float m0 = -1e30f, m1 = -1e30f, l0 = 0.f, l1 = 0.f;
    float oAcc[32][4];
    #pragma unroll
    for (int n = 0; n < 32; n++)
        #pragma unroll
        for (int c = 0; c < 4; c++) oAcc[n][c] = 0.f;

    // ldmatrix per-lane address components (constant across loop)
    const uint32_t arow  = wid*16 + (lane & 15);
    const uint32_t acol0 = (lane >> 4) * 8;
    const uint32_t btok  = ((lane >> 4) & 1)*8 + (lane & 7);
    const uint32_t bkoff = ((lane >> 3) & 1)*8;

    for (int kt = 0; kt < 64; kt++) {
        __syncthreads();                         // prior tile fully consumed
        if (kt < 63) { issue_kv(sb, Kp, Vp, kt+1, (kt+1)&1, tid); CP_WAIT(1); }
        else         { CP_WAIT(0); }
        __syncthreads();                         // tile kt visible to all warps

        uint32_t kbase = sb + SM_K + (kt&1)*SM_KBUF;
        uint32_t vbase = sb + SM_V + (kt&1)*SM_VBUF;

        // ---- S = Q K^T : per warp 16x64, 16 k-steps ----
        float sAcc[8][4] = {};
        #pragma unroll
        for (int s = 0; s < 16; s++) {
            uint32_t a[4];
            LDSM4(a, sb + (uint32_t)((arow*QSTR + s*16 + acol0)*2));
            #pragma unroll
            for (int j2 = 0; j2 < 4; j2++) {
                uint32_t b[4];
                LDSM4(b, kbase + (uint32_t)(((j2*16 + btok)*KSTR + s*16 + bkoff)*2));
                mma16816(sAcc[2*j2],   a, b);
                mma16816(sAcc[2*j2+1], a, b + 2);
            }
        }

        // ---- online softmax (rows r0 = g, r1 = g+8; reduce across quad) ----
        float pm0 = -1e30f, pm1 = -1e30f;
        #pragma unroll
        for (int j = 0; j < 8; j++) {
            pm0 = fmaxf(pm0, fmaxf(sAcc[j][0], sAcc[j][1]));
            pm1 = fmaxf(pm1, fmaxf(sAcc[j][2], sAcc[j][3]));
        }
        pm0 = fmaxf(pm0, __shfl_xor_sync(0xffffffffu, pm0, 1));
        pm0 = fmaxf(pm0, __shfl_xor_sync(0xffffffffu, pm0, 2));
        pm1 = fmaxf(pm1, __shfl_xor_sync(0xffffffffu, pm1, 1));
        pm1 = fmaxf(pm1, __shfl_xor_sync(0xffffffffu, pm1, 2));
        float mn0 = fmaxf(m0, pm0), mn1 = fmaxf(m1, pm1);
        float al0 = __expf(m0 - mn0), al1 = __expf(m1 - mn1);

        float rs0 = 0.f, rs1 = 0.f;
        uint32_t pfrag[4][4];
        #pragma unroll
        for (int j = 0; j < 8; j++) {
            float p0 = __expf(sAcc[j][0] - mn0);
            float p1 = __expf(sAcc[j][1] - mn0);
            float p2 = __expf(sAcc[j][2] - mn1);
            float p3 = __expf(sAcc[j][3] - mn1);
            rs0 += p0 + p1; rs1 += p2 + p3;
            __nv_bfloat162 u01 = __floats2bfloat162_rn(p0, p1);
            __nv_bfloat162 u23 = __floats2bfloat162_rn(p2, p3);
            int s = j >> 1, hi = j & 1;
            pfrag[s][hi*2 + 0] = *(uint32_t*)&u01;   // A reg a0 (or a2)
            pfrag[s][hi*2 + 1] = *(uint32_t*)&u23;   // A reg a1 (or a3)
        }
        rs0 += __shfl_xor_sync(0xffffffffu, rs0, 1);
        rs0 += __shfl_xor_sync(0xffffffffu, rs0, 2);
        rs1 += __shfl_xor_sync(0xffffffffu, rs1, 1);
        rs1 += __shfl_xor_sync(0xffffffffu, rs1, 2);
        l0 = al0*l0 + rs0; l1 = al1*l1 + rs1;
        m0 = mn0; m1 = mn1;

        #pragma unroll
        for (int n = 0; n < 32; n++) {
            oAcc[n][0] *= al0; oAcc[n][1] *= al0;
            oAcc[n][2] *= al1; oAcc[n][3] *= al1;
        }

        // ---- O += P V : 4 k-steps (16 tokens), 32 n-tiles (256 ch) ----
        #pragma unroll
        for (int s = 0; s < 4; s++) {
            #pragma unroll
            for (int n2 = 0; n2 < 16; n2++) {
                uint32_t b[4];
                uint32_t ch = n2*16 + ((lane >> 4) & 1)*8 + (lane & 7);
                uint32_t tok = s*16 + ((lane >> 3) & 1)*8;
                LDSM4(b, vbase + (uint32_t)((ch*VSTR + tok)*2));
                mma16816(oAcc[2*n2],   pfrag[s], b);
                mma16816(oAcc[2*n2+1], pfrag[s], b + 2);
            }
        }
    }

    // ---- epilogue: O / l -> g_ao ----
    float inv0 = 1.f / l0, inv1 = 1.f / l1;
    float* AO = g_ao + (size_t)bb * Nt * Ct;
    int r0 = n0 + wid*16 + g, r1 = r0 + 8;
    #pragma unroll
    for (int n = 0; n < 32; n++) {
        int ch = n*8 + tig*2;
        *(float2*)&AO[(size_t)r0*Ct + ch] = make_float2(oAcc[n][0]*inv0, oAcc[n][1]*inv0);
        *(float2*)&AO[(size_t)r1*Ct + ch] = make_float2(oAcc[n][2]*inv1, oAcc[n][3]*inv1);
    }
}

// ---------------------------------------------------------------------------
// Output projection + residual
// ---------------------------------------------------------------------------
__global__ __launch_bounds__(256) void oproj_kernel(const float* __restrict__ w,
                                                    const float* __restrict__ bias,
                                                    const float* __restrict__ x,
                                                    float* __restrict__ out) {
    __shared__ float As[64*17];
    __shared__ float Ws[64*17];
    int tid = threadIdx.x, tx = tid & 15, ty = tid >> 4;
    int n0 = blockIdx.x * 64, o0 = blockIdx.y * 64, bb = blockIdx.z;
    const float* A = g_ao + (size_t)bb * Nt * Ct;

    float acc[4][4] = {};
    for (int kt = 0; kt < 16; kt++) {
        #pragma unroll
        for (int i = 0; i < 4; i++) {
            int e = tid + i*256;
            int r = e >> 4, c = e & 15;
            As[r*17 + c] = A[(size_t)(n0 + r)*Ct + kt*16 + c];
            Ws[r*17 + c] = w[(o0 + r)*Ct + kt*16 + c];
        }
        __syncthreads();
        #pragma unroll
        for (int k = 0; k < 16; k++) {
            float wv[4], av[4];
            #pragma unroll
            for (int i = 0; i < 4; i++) wv[i] = Ws[(ty*4+i)*17 + k];
            #pragma unroll
            for (int j = 0; j < 4; j++) av[j] = As[(tx*4+j)*17 + k];
            #pragma unroll
            for (int i = 0; i < 4; i++)
                #pragma unroll
                for (int j = 0; j < 4; j++) acc[i][j] += wv[i]*av[j];
        }
        __syncthreads();
    }
    #pragma unroll
    for (int i = 0; i < 4; i++) {
        int o = o0 + ty*4 + i;
        size_t base = ((size_t)bb*Ct + o)*Nt + n0 + tx*4;
        float4 xv = *(const float4*)&x[base];
        float bo_ = bias[o];
        float4 ov;
        ov.x = acc[i][0] + bo_ + xv.x;
        ov.y = acc[i][1] + bo_ + xv.y;
        ov.z = acc[i][2] + bo_ + xv.z;
        ov.w = acc[i][3] + bo_ + xv.w;
        *(float4*)&out[base] = ov;
    }
}

// ---------------------------------------------------------------------------
extern "C" void kernel_launch(void* const* d_in, const int* in_sizes, int n_in,
                              void* d_out, int out_size) {
    (void)in_sizes; (void)n_in; (void)out_size;
    const float* x   = (const float*)d_in[0];
    const float* gnw = (const float*)d_in[1];
    const float* gnb = (const float*)d_in[2];
    const float* wq  = (const float*)d_in[3];
    const float* bq  = (const float*)d_in[4];
    const float* wk  = (const float*)d_in[5];
    const float* bk  = (const float*)d_in[6];
    const float* wv  = (const float*)d_in[7];
    const float* bv  = (const float*)d_in[8];
    const float* wo  = (const float*)d_in[9];
    const float* bo  = (const float*)d_in[10];
    float* out = (float*)d_out;

    cudaFuncSetAttribute(flash_mma, cudaFuncAttributeMaxDynamicSharedMemorySize, FLASH_SMEM);

    gn_kernel<<<256, 256>>>(x, gnw, gnb);

    dim3 pg(Nt/64, Ct/64, Bt);
    proj_kernel<<<pg, 256>>>(wq, bq, 0, 0.0625f);  // Q, scaled by 1/sqrt(C)
    proj_kernel<<<pg, 256>>>(wk, bk, 1, 1.0f);
    proj_kernel<<<pg, 256>>>(wv, bv, 2, 1.0f);

    dim3 fg(Nt/128, Bt);
    flash_mma<<<fg, 256, FLASH_SMEM>>>();

    oproj_kernel<<<pg, 256>>>(wo, bo, x, out);
}

// round 9
// speedup vs baseline: 10.4165x; 1.6717x over previous
#include <cuda_runtime.h>
#include <cuda_bf16.h>
#include <stdint.h>
#include <math.h>

#define Bt 8
#define Ct 256
#define Nt 4096

// Scratch (device globals — no allocations allowed)
__device__ __nv_bfloat16 g_hb [Bt*Nt*Ct];  // groupnorm out, [B][N][C] bf16
__device__ __nv_bfloat16 g_qb [Bt*Nt*Ct];  // [B][N][C] bf16, pre-scaled 1/16
__device__ __nv_bfloat16 g_kb [Bt*Nt*Ct];  // [B][N][C] bf16
__device__ __nv_bfloat16 g_vb [Bt*Ct*Nt];  // [B][C][N] bf16 (channel-major)
__device__ __nv_bfloat16 g_aob[Bt*Nt*Ct];  // attention out, [B][N][C] bf16

// ===========================================================================
// sm_80-class tensor-core primitives (legal on base compute_103)
// ===========================================================================
__device__ __forceinline__ uint32_t cvta_smem(const void* p) {
    uint32_t a;
    asm("{ .reg .u64 t; cvta.to.shared.u64 t, %1; cvt.u32.u64 %0, t; }" : "=r"(a) : "l"(p));
    return a;
}
#define LDSM4(r, a) \
    asm volatile("ldmatrix.sync.aligned.m8n8.x4.shared.b16 {%0,%1,%2,%3}, [%4];" \
        : "=r"((r)[0]), "=r"((r)[1]), "=r"((r)[2]), "=r"((r)[3]) : "r"(a))

__device__ __forceinline__ void mma16816(float* d, const uint32_t* a, const uint32_t* b) {
    asm volatile("mma.sync.aligned.m16n8k16.row.col.f32.bf16.bf16.f32 "
        "{%0,%1,%2,%3}, {%4,%5,%6,%7}, {%8,%9}, {%0,%1,%2,%3};"
        : "+f"(d[0]), "+f"(d[1]), "+f"(d[2]), "+f"(d[3])
        : "r"(a[0]), "r"(a[1]), "r"(a[2]), "r"(a[3]), "r"(b[0]), "r"(b[1]));
}
#define CP_ASYNC16(s, g) \
    asm volatile("cp.async.cg.shared.global [%0], [%1], 16;" :: "r"(s), "l"(g))
#define CP_COMMIT()  asm volatile("cp.async.commit_group;")
#define CP_WAIT(N)   asm volatile("cp.async.wait_group %0;" :: "n"(N))

// ---------------------------------------------------------------------------
// GroupNorm -> bf16 h in [B][N][C] (packed 8-channel uint4 stores)
// ---------------------------------------------------------------------------
__global__ __launch_bounds__(256) void gn_kernel(const float* __restrict__ x,
                                                 const float* __restrict__ w,
                                                 const float* __restrict__ b) {
    int bg = blockIdx.x;
    int batch = bg >> 5, g = bg & 31;
    const float* xp = x + ((size_t)(batch*Ct + g*8)) * Nt;
    int tid = threadIdx.x;

    float s = 0.f, ss = 0.f;
    for (int i = tid; i < 8*Nt; i += 256) { float v = xp[i]; s += v; ss += v*v; }

    __shared__ float r1[256], r2[256];
    r1[tid] = s; r2[tid] = ss;
    __syncthreads();
    for (int st = 128; st > 0; st >>= 1) {
        if (tid < st) { r1[tid] += r1[tid+st]; r2[tid] += r2[tid+st]; }
        __syncthreads();
    }
    __shared__ float sc[8], sh[8];
    if (tid < 8) {
        float mean = r1[0] * (1.f/32768.f);
        float var  = r2[0] * (1.f/32768.f) - mean*mean;
        float rstd = rsqrtf(var + 1e-5f);
        float scale = w[g*8 + tid] * rstd;
        sc[tid] = scale;
        sh[tid] = b[g*8 + tid] - mean * scale;
    }
    __syncthreads();

    __nv_bfloat16* hb = g_hb + (size_t)batch * Nt * Ct + g*8;
    for (int it = 0; it < 16; it++) {
        int n = it*256 + tid;
        float v[8];
        #pragma unroll
        for (int c = 0; c < 8; c++) v[c] = xp[c*Nt + n]*sc[c] + sh[c];
        uint4 u;
        __nv_bfloat162 p0 = __floats2bfloat162_rn(v[0], v[1]);
        __nv_bfloat162 p1 = __floats2bfloat162_rn(v[2], v[3]);
        __nv_bfloat162 p2 = __floats2bfloat162_rn(v[4], v[5]);
        __nv_bfloat162 p3 = __floats2bfloat162_rn(v[6], v[7]);
        u.x = *(uint32_t*)&p0; u.y = *(uint32_t*)&p1;
        u.z = *(uint32_t*)&p2; u.w = *(uint32_t*)&p3;
        *(uint4*)&hb[(size_t)n*Ct] = u;
    }
}

// ---------------------------------------------------------------------------
// Tensor-core 256x256 projection GEMM. CTA: 128 tokens x 256 outs, K=256.
// mode: 0=Q([n][o] bf16, *1/16)  1=K([n][o] bf16)  2=V([o][n] bf16)
//       3=O-proj (fp32 out[o][n] + bias + residual x)
// ---------------------------------------------------------------------------
#define WSTR 264
#define ASTR 264
#define GM_W    0
#define GM_R2   (256*WSTR*2)             // 135168
#define GM_BIAS (GM_R2 + 69632)          // region2: max(A 67584, V-stage 69632)
#define GEMM_SMEM (GM_BIAS + 1024)       // 205824

__global__ __launch_bounds__(256, 1) void gemm256(const float* __restrict__ w,
                                                  const float* __restrict__ bias,
                                                  const float* __restrict__ xres,
                                                  float* __restrict__ outp,
                                                  int mode) {
    extern __shared__ char sm[];
    __nv_bfloat16* Wt = (__nv_bfloat16*)(sm + GM_W);     // [256][WSTR]
    __nv_bfloat16* At = (__nv_bfloat16*)(sm + GM_R2);    // [128][ASTR]
    float* bsh = (float*)(sm + GM_BIAS);
    const uint32_t sb = cvta_smem(sm);
    const int tid = threadIdx.x, lane = tid & 31, wid = tid >> 5;
    const int g = lane >> 2, tig = lane & 3;
    const int n0 = blockIdx.x * 128, bb = blockIdx.y;
    const __nv_bfloat16* A = ((mode < 3) ? g_hb : g_aob) + (size_t)bb * Nt * Ct;

    // W fp32 -> bf16 smem
    #pragma unroll 8
    for (int i = 0; i < 128; i++) {
        int e = tid + i*256;
        int row = e >> 7, c2 = e & 127;
        float2 f = *(const float2*)&w[row*256 + c2*2];
        __nv_bfloat162 bp = __floats2bfloat162_rn(f.x, f.y);
        *(uint32_t*)&Wt[row*WSTR + c2*2] = *(uint32_t*)&bp;
    }
    bsh[tid] = bias[tid];
    // A tile
    #pragma unroll
    for (int i = 0; i < 16; i++) {
        int e = tid + i*256;
        int r = e >> 5, c8 = e & 31;
        *(uint4*)&At[r*ASTR + c8*8] = *(const uint4*)&A[(size_t)(n0 + r)*Ct + c8*8];
    }
    __syncthreads();

    float acc[32][4];
    #pragma unroll
    for (int n = 0; n < 32; n++)
        #pragma unroll
        for (int c = 0; c < 4; c++) acc[n][c] = 0.f;

    const uint32_t arow  = wid*16 + (lane & 15);
    const uint32_t acol0 = (lane >> 4) * 8;
    const uint32_t brow  = ((lane >> 4) & 1)*8 + (lane & 7);
    const uint32_t bk    = ((lane >> 3) & 1)*8;
    const uint32_t abase = sb + GM_R2;

    #pragma unroll
    for (int s = 0; s < 16; s++) {
        uint32_t a[4];
        LDSM4(a, abase + (uint32_t)((arow*ASTR + s*16 + acol0)*2));
        #pragma unroll
        for (int j2 = 0; j2 < 16; j2++) {
            uint32_t b[4];
            LDSM4(b, sb + (uint32_t)(((j2*16 + brow)*WSTR + s*16 + bk)*2));
            mma16816(acc[2*j2],   a, b);
            mma16816(acc[2*j2+1], a, b + 2);
        }
    }
    __syncthreads();                       // A consumed; region2 reusable

    const int rlo = wid*16 + g, rhi = rlo + 8;

    if (mode <= 1) {                       // Q/K: stage [n][o] bf16
        float scale = (mode == 0) ? 0.0625f : 1.f;
        __nv_bfloat16* SD = (__nv_bfloat16*)(sm + GM_R2);
        #pragma unroll
        for (int j2 = 0; j2 < 16; j2++)
            #pragma unroll
            for (int hi = 0; hi < 2; hi++) {
                int o = j2*16 + hi*8 + tig*2;
                float* ac = acc[2*j2 + hi];
                __nv_bfloat162 plo = __floats2bfloat162_rn((ac[0]+bsh[o])*scale, (ac[1]+bsh[o+1])*scale);
                __nv_bfloat162 phi = __floats2bfloat162_rn((ac[2]+bsh[o])*scale, (ac[3]+bsh[o+1])*scale);
                *(uint32_t*)&SD[rlo*264 + o] = *(uint32_t*)&plo;
                *(uint32_t*)&SD[rhi*264 + o] = *(uint32_t*)&phi;
            }
        __syncthreads();
        __nv_bfloat16* outb = ((mode == 0) ? g_qb : g_kb) + (size_t)bb * Nt * Ct;
        #pragma unroll
        for (int i = 0; i < 16; i++) {
            int e = tid + i*256;
            int r = e >> 5, c8 = e & 31;
            *(uint4*)&outb[(size_t)(n0 + r)*Ct + c8*8] = *(uint4*)&SD[r*264 + c8*8];
        }
    } else if (mode == 2) {                // V: stage [o][n] bf16
        __nv_bfloat16* SD = (__nv_bfloat16*)(sm + GM_R2);
        #pragma unroll
        for (int j2 = 0; j2 < 16; j2++)
            #pragma unroll
            for (int hi = 0; hi < 2; hi++) {
                int o = j2*16 + hi*8 + tig*2;
                float* ac = acc[2*j2 + hi];
                SD[o*136 + rlo]     = __float2bfloat16(ac[0] + bsh[o]);
                SD[(o+1)*136 + rlo] = __float2bfloat16(ac[1] + bsh[o+1]);
                SD[o*136 + rhi]     = __float2bfloat16(ac[2] + bsh[o]);
                SD[(o+1)*136 + rhi] = __float2bfloat16(ac[3] + bsh[o+1]);
            }
        __syncthreads();
        __nv_bfloat16* outb = g_vb + (size_t)bb * Ct * Nt;
        #pragma unroll
        for (int i = 0; i < 16; i++) {
            int e = tid + i*256;
            int r = e >> 4, c8 = e & 15;
            *(uint4*)&outb[(size_t)r*Nt + n0 + c8*8] = *(uint4*)&SD[r*136 + c8*8];
        }
    } else {                               // O-proj: fp32 [o][n] + bias + x
        float* SD = (float*)(sm + GM_R2);  // [128][132]
        #pragma unroll
        for (int half = 0; half < 2; half++) {
            #pragma unroll
            for (int j2 = half*8; j2 < half*8 + 8; j2++)
                #pragma unroll
                for (int hi = 0; hi < 2; hi++) {
                    int o = j2*16 + hi*8 + tig*2;
                    int ol = o - half*128;
                    float* ac = acc[2*j2 + hi];
                    SD[ol*132 + rlo]     = ac[0];
                    SD[(ol+1)*132 + rlo] = ac[1];
                    SD[ol*132 + rhi]     = ac[2];
                    SD[(ol+1)*132 + rhi] = ac[3];
                }
            __syncthreads();
            #pragma unroll
            for (int i = 0; i < 16; i++) {
                int e = tid + i*256;
                int r = e >> 5, c4 = e & 31;
                int o = half*128 + r;
                size_t base = ((size_t)bb*Ct + o)*Nt + n0 + c4*4;
                float4 v  = *(float4*)&SD[r*132 + c4*4];
                float4 xv = *(const float4*)&xres[base];
                float bo = bsh[o];
                v.x += bo + xv.x; v.y += bo + xv.y;
                v.z += bo + xv.z; v.w += bo + xv.w;
                *(float4*)&outp[base] = v;
            }
            __syncthreads();
        }
    }
}

// ---------------------------------------------------------------------------
// Flash attention via mma.sync (bf16, fp32 acc). Br=128 (8 warps x 16 rows),
// Bc=64, D=256. K/V double-buffered via cp.async.
// ---------------------------------------------------------------------------
#define QSTR 264
#define KSTR 264
#define VSTR 72
#define SM_K    (128*QSTR*2)
#define SM_KBUF (64*KSTR*2)
#define SM_V    (SM_K + 2*SM_KBUF)
#define SM_VBUF (256*VSTR*2)
#define FLASH_SMEM (SM_V + 2*SM_VBUF)   // 208896

__device__ __forceinline__ void issue_kv(uint32_t sb,
                                         const __nv_bfloat16* Kp,
                                         const __nv_bfloat16* Vp,
                                         int kt, int buf, int tid) {
    uint32_t kbase = sb + SM_K + buf*SM_KBUF;
    #pragma unroll
    for (int i = 0; i < 8; i++) {
        int e = tid + i*256;
        int r = e >> 5, c8 = e & 31;
        CP_ASYNC16(kbase + (uint32_t)(r*KSTR + c8*8)*2,
                   (const void*)&Kp[(size_t)(kt*64 + r)*Ct + c8*8]);
    }
    uint32_t vbase = sb + SM_V + buf*SM_VBUF;
    #pragma unroll
    for (int i = 0; i < 8; i++) {
        int e = tid + i*256;
        int r = e >> 3, c8 = e & 7;
        CP_ASYNC16(vbase + (uint32_t)(r*VSTR + c8*8)*2,
                   (const void*)&Vp[(size_t)r*Nt + kt*64 + c8*8]);
    }
    CP_COMMIT();
}

__global__ __launch_bounds__(256, 1) void flash_mma() {
    extern __shared__ char smem[];
    const uint32_t sb = cvta_smem(smem);
    const int tid = threadIdx.x, lane = tid & 31, wid = tid >> 5;
    const int g = lane >> 2, tig = lane & 3;
    const int n0 = blockIdx.x * 128, bb = blockIdx.y;
    const __nv_bfloat16* Qp = g_qb + (size_t)bb * Nt * Ct;
    const __nv_bfloat16* Kp = g_kb + (size_t)bb * Nt * Ct;
    const __nv_bfloat16* Vp = g_vb + (size_t)bb * Ct * Nt;

    issue_kv(sb, Kp, Vp, 0, 0, tid);

    #pragma unroll
    for (int i = 0; i < 16; i++) {
        int e = tid + i*256;
        int r = e >> 5, c8 = e & 31;
        uint4 u = *(const uint4*)&Qp[(size_t)(n0 + r)*Ct + c8*8];
        *(uint4*)(smem + (size_t)(r*QSTR + c8*8)*2) = u;
    }

    float m0 = -1e30f, m1 = -1e30f, l0 = 0.f, l1 = 0.f;
    float oAcc[32][4];
    #pragma unroll
    for (int n = 0; n < 32; n++)
        #pragma unroll
        for (int c = 0; c < 4; c++) oAcc[n][c] = 0.f;

    const uint32_t arow  = wid*16 + (lane & 15);
    const uint32_t acol0 = (lane >> 4) * 8;
    const uint32_t btok  = ((lane >> 4) & 1)*8 + (lane & 7);
    const uint32_t bkoff = ((lane >> 3) & 1)*8;

    for (int kt = 0; kt < 64; kt++) {
        __syncthreads();
        if (kt < 63) { issue_kv(sb, Kp, Vp, kt+1, (kt+1)&1, tid); CP_WAIT(1); }
        else         { CP_WAIT(0); }
        __syncthreads();

        uint32_t kbase = sb + SM_K + (kt&1)*SM_KBUF;
        uint32_t vbase = sb + SM_V + (kt&1)*SM_VBUF;

        float sAcc[8][4] = {};
        #pragma unroll
        for (int s = 0; s < 16; s++) {
            uint32_t a[4];
            LDSM4(a, sb + (uint32_t)((arow*QSTR + s*16 + acol0)*2));
            #pragma unroll
            for (int j2 = 0; j2 < 4; j2++) {
                uint32_t b[4];
                LDSM4(b, kbase + (uint32_t)(((j2*16 + btok)*KSTR + s*16 + bkoff)*2));
                mma16816(sAcc[2*j2],   a, b);
                mma16816(sAcc[2*j2+1], a, b + 2);
            }
        }

        float pm0 = -1e30f, pm1 = -1e30f;
        #pragma unroll
        for (int j = 0; j < 8; j++) {
            pm0 = fmaxf(pm0, fmaxf(sAcc[j][0], sAcc[j][1]));
            pm1 = fmaxf(pm1, fmaxf(sAcc[j][2], sAcc[j][3]));
        }
        pm0 = fmaxf(pm0, __shfl_xor_sync(0xffffffffu, pm0, 1));
        pm0 = fmaxf(pm0, __shfl_xor_sync(0xffffffffu, pm0, 2));
        pm1 = fmaxf(pm1, __shfl_xor_sync(0xffffffffu, pm1, 1));
        pm1 = fmaxf(pm1, __shfl_xor_sync(0xffffffffu, pm1, 2));
        float mn0 = fmaxf(m0, pm0), mn1 = fmaxf(m1, pm1);
        float al0 = __expf(m0 - mn0), al1 = __expf(m1 - mn1);

        float rs0 = 0.f, rs1 = 0.f;
        uint32_t pfrag[4][4];
        #pragma unroll
        for (int j = 0; j < 8; j++) {
            float p0 = __expf(sAcc[j][0] - mn0);
            float p1 = __expf(sAcc[j][1] - mn0);
            float p2 = __expf(sAcc[j][2] - mn1);
            float p3 = __expf(sAcc[j][3] - mn1);
            rs0 += p0 + p1; rs1 += p2 + p3;
            __nv_bfloat162 u01 = __floats2bfloat162_rn(p0, p1);
            __nv_bfloat162 u23 = __floats2bfloat162_rn(p2, p3);
            int s = j >> 1, hi = j & 1;
            pfrag[s][hi*2 + 0] = *(uint32_t*)&u01;
            pfrag[s][hi*2 + 1] = *(uint32_t*)&u23;
        }
        rs0 += __shfl_xor_sync(0xffffffffu, rs0, 1);
        rs0 += __shfl_xor_sync(0xffffffffu, rs0, 2);
        rs1 += __shfl_xor_sync(0xffffffffu, rs1, 1);
        rs1 += __shfl_xor_sync(0xffffffffu, rs1, 2);
        l0 = al0*l0 + rs0; l1 = al1*l1 + rs1;
        m0 = mn0; m1 = mn1;

        #pragma unroll
        for (int n = 0; n < 32; n++) {
            oAcc[n][0] *= al0; oAcc[n][1] *= al0;
            oAcc[n][2] *= al1; oAcc[n][3] *= al1;
        }

        #pragma unroll
        for (int s = 0; s < 4; s++) {
            #pragma unroll
            for (int n2 = 0; n2 < 16; n2++) {
                uint32_t b[4];
                uint32_t ch = n2*16 + ((lane >> 4) & 1)*8 + (lane & 7);
                uint32_t tok = s*16 + ((lane >> 3) & 1)*8;
                LDSM4(b, vbase + (uint32_t)((ch*VSTR + tok)*2));
                mma16816(oAcc[2*n2],   pfrag[s], b);
                mma16816(oAcc[2*n2+1], pfrag[s], b + 2);
            }
        }
    }

    // epilogue: O / l -> g_aob (bf16, [N][C])
    float inv0 = 1.f / l0, inv1 = 1.f / l1;
    __nv_bfloat16* AO = g_aob + (size_t)bb * Nt * Ct;
    int r0 = n0 + wid*16 + g, r1 = r0 + 8;
    #pragma unroll
    for (int n = 0; n < 32; n++) {
        int ch = n*8 + tig*2;
        __nv_bfloat162 u0 = __floats2bfloat162_rn(oAcc[n][0]*inv0, oAcc[n][1]*inv0);
        __nv_bfloat162 u1 = __floats2bfloat162_rn(oAcc[n][2]*inv1, oAcc[n][3]*inv1);
        *(uint32_t*)&AO[(size_t)r0*Ct + ch] = *(uint32_t*)&u0;
        *(uint32_t*)&AO[(size_t)r1*Ct + ch] = *(uint32_t*)&u1;
    }
}

// ---------------------------------------------------------------------------
extern "C" void kernel_launch(void* const* d_in, const int* in_sizes, int n_in,
                              void* d_out, int out_size) {
    (void)in_sizes; (void)n_in; (void)out_size;
    const float* x   = (const float*)d_in[0];
    const float* gnw = (const float*)d_in[1];
    const float* gnb = (const float*)d_in[2];
    const float* wq  = (const float*)d_in[3];
    const float* bq  = (const float*)d_in[4];
    const float* wk  = (const float*)d_in[5];
    const float* bk  = (const float*)d_in[6];
    const float* wv  = (const float*)d_in[7];
    const float* bv  = (const float*)d_in[8];
    const float* wo  = (const float*)d_in[9];
    const float* bo  = (const float*)d_in[10];
    float* out = (float*)d_out;

    cudaFuncSetAttribute(flash_mma, cudaFuncAttributeMaxDynamicSharedMemorySize, FLASH_SMEM);
    cudaFuncSetAttribute(gemm256,   cudaFuncAttributeMaxDynamicSharedMemorySize, GEMM_SMEM);

    gn_kernel<<<256, 256>>>(x, gnw, gnb);

    dim3 gg(Nt/128, Bt);
    gemm256<<<gg, 256, GEMM_SMEM>>>(wq, bq, nullptr, nullptr, 0);
    gemm256<<<gg, 256, GEMM_SMEM>>>(wk, bk, nullptr, nullptr, 1);
    gemm256<<<gg, 256, GEMM_SMEM>>>(wv, bv, nullptr, nullptr, 2);

    flash_mma<<<gg, 256, FLASH_SMEM>>>();

    gemm256<<<gg, 256, GEMM_SMEM>>>(wo, bo, x, out, 3);
}

// round 12
// speedup vs baseline: 11.3445x; 1.0891x over previous
#include <cuda_runtime.h>
#include <cuda_bf16.h>
#include <stdint.h>
#include <math.h>

#define Bt 8
#define Ct 256
#define Nt 4096
#define LOG2E 1.44269504088896f

// Scratch (device globals — no allocations allowed)
__device__ __nv_bfloat16 g_hb [Bt*Nt*Ct];  // groupnorm out, [B][N][C] bf16
__device__ __nv_bfloat16 g_qb [Bt*Nt*Ct];  // [B][N][C] bf16, scale = log2e/16
__device__ __nv_bfloat16 g_kb [Bt*Nt*Ct];  // [B][N][C] bf16
__device__ __nv_bfloat16 g_vb [Bt*Nt*Ct];  // [B][N][C] bf16
__device__ __nv_bfloat16 g_aob[Bt*Nt*Ct];  // attention out, [B][N][C] bf16
__device__ __nv_bfloat16 g_wb [4*Ct*Ct];   // pre-converted weights bf16 (q,k,v,o)

// ===========================================================================
__device__ __forceinline__ uint32_t cvta_smem(const void* p) {
    uint32_t a;
    asm("{ .reg .u64 t; cvta.to.shared.u64 t, %1; cvt.u32.u64 %0, t; }" : "=r"(a) : "l"(p));
    return a;
}
#define LDSM4(r, a) \
    asm volatile("ldmatrix.sync.aligned.m8n8.x4.shared.b16 {%0,%1,%2,%3}, [%4];" \
        : "=r"((r)[0]), "=r"((r)[1]), "=r"((r)[2]), "=r"((r)[3]) : "r"(a))
#define LDSM4T(r, a) \
    asm volatile("ldmatrix.sync.aligned.m8n8.x4.trans.shared.b16 {%0,%1,%2,%3}, [%4];" \
        : "=r"((r)[0]), "=r"((r)[1]), "=r"((r)[2]), "=r"((r)[3]) : "r"(a))

__device__ __forceinline__ void mma16816(float* d, const uint32_t* a, const uint32_t* b) {
    asm volatile("mma.sync.aligned.m16n8k16.row.col.f32.bf16.bf16.f32 "
        "{%0,%1,%2,%3}, {%4,%5,%6,%7}, {%8,%9}, {%0,%1,%2,%3};"
        : "+f"(d[0]), "+f"(d[1]), "+f"(d[2]), "+f"(d[3])
        : "r"(a[0]), "r"(a[1]), "r"(a[2]), "r"(a[3]), "r"(b[0]), "r"(b[1]));
}
#define CP_ASYNC16(s, g) \
    asm volatile("cp.async.cg.shared.global [%0], [%1], 16;" :: "r"(s), "l"(g))
#define CP_COMMIT()  asm volatile("cp.async.commit_group;")
#define CP_WAIT(N)   asm volatile("cp.async.wait_group %0;" :: "n"(N))

// ---------------------------------------------------------------------------
// Weight pre-conversion: 4 x 256x256 fp32 -> bf16
// ---------------------------------------------------------------------------
__global__ __launch_bounds__(256) void wcvt(const float* __restrict__ wq,
                                            const float* __restrict__ wk,
                                            const float* __restrict__ wv,
                                            const float* __restrict__ wo) {
    int idx = (blockIdx.x*256 + threadIdx.x) * 4;     // grid 256 -> 262144 elems
    const float* src = (idx < 65536) ? wq : (idx < 131072) ? wk
                     : (idx < 196608) ? wv : wo;
    float4 f = *(const float4*)&src[idx & 65535];
    __nv_bfloat162 p0 = __floats2bfloat162_rn(f.x, f.y);
    __nv_bfloat162 p1 = __floats2bfloat162_rn(f.z, f.w);
    uint2 u; u.x = *(uint32_t*)&p0; u.y = *(uint32_t*)&p1;
    *(uint2*)&g_wb[idx] = u;
}

// ---------------------------------------------------------------------------
// GroupNorm -> bf16 h in [B][N][C]
// ---------------------------------------------------------------------------
__global__ __launch_bounds__(256) void gn_kernel(const float* __restrict__ x,
                                                 const float* __restrict__ w,
                                                 const float* __restrict__ b) {
    int bg = blockIdx.x;
    int batch = bg >> 5, g = bg & 31;
    const float* xp = x + ((size_t)(batch*Ct + g*8)) * Nt;
    int tid = threadIdx.x;

    float s = 0.f, ss = 0.f;
    for (int i = tid; i < 8*Nt; i += 256) { float v = xp[i]; s += v; ss += v*v; }

    __shared__ float r1[256], r2[256];
    r1[tid] = s; r2[tid] = ss;
    __syncthreads();
    for (int st = 128; st > 0; st >>= 1) {
        if (tid < st) { r1[tid] += r1[tid+st]; r2[tid] += r2[tid+st]; }
        __syncthreads();
    }
    __shared__ float sc[8], sh[8];
    if (tid < 8) {
        float mean = r1[0] * (1.f/32768.f);
        float var  = r2[0] * (1.f/32768.f) - mean*mean;
        float rstd = rsqrtf(var + 1e-5f);
        float scale = w[g*8 + tid] * rstd;
        sc[tid] = scale;
        sh[tid] = b[g*8 + tid] - mean * scale;
    }
    __syncthreads();

    __nv_bfloat16* hb = g_hb + (size_t)batch * Nt * Ct + g*8;
    for (int it = 0; it < 16; it++) {
        int n = it*256 + tid;
        float v[8];
        #pragma unroll
        for (int c = 0; c < 8; c++) v[c] = xp[c*Nt + n]*sc[c] + sh[c];
        uint4 u;
        __nv_bfloat162 p0 = __floats2bfloat162_rn(v[0], v[1]);
        __nv_bfloat162 p1 = __floats2bfloat162_rn(v[2], v[3]);
        __nv_bfloat162 p2 = __floats2bfloat162_rn(v[4], v[5]);
        __nv_bfloat162 p3 = __floats2bfloat162_rn(v[6], v[7]);
        u.x = *(uint32_t*)&p0; u.y = *(uint32_t*)&p1;
        u.z = *(uint32_t*)&p2; u.w = *(uint32_t*)&p3;
        *(uint4*)&hb[(size_t)n*Ct] = u;
    }
}

// ---------------------------------------------------------------------------
// Fused QKV GEMM: one CTA = 128 tokens x 256 outs, K=256; 3 phases (Q,K,V),
// A tile resident, bf16 W streamed per phase, W region reused as store stage.
// ---------------------------------------------------------------------------
#define GW 0                         // W region: 256x264 bf16 = 135168
#define GA 135168                    // A region: 128x264 bf16 = 67584
#define QKV_SMEM 202752

__global__ __launch_bounds__(256, 1) void qkv_gemm(const float* __restrict__ bq,
                                                   const float* __restrict__ bk,
                                                   const float* __restrict__ bv) {
    extern __shared__ char sm[];
    __nv_bfloat16* Wt = (__nv_bfloat16*)(sm + GW);
    __nv_bfloat16* At = (__nv_bfloat16*)(sm + GA);
    const uint32_t sb = cvta_smem(sm);
    const int tid = threadIdx.x, lane = tid & 31, wid = tid >> 5;
    const int g = lane >> 2, tig = lane & 3;
    const int n0 = blockIdx.x * 128, bb = blockIdx.y;
    const __nv_bfloat16* A = g_hb + (size_t)bb * Nt * Ct;

    #pragma unroll
    for (int i = 0; i < 16; i++) {
        int e = tid + i*256;
        int r = e >> 5, c8 = e & 31;
        *(uint4*)&At[r*264 + c8*8] = *(const uint4*)&A[(size_t)(n0 + r)*Ct + c8*8];
    }

    const uint32_t arow  = wid*16 + (lane & 15);
    const uint32_t acol0 = (lane >> 4) * 8;
    const uint32_t brow  = ((lane >> 4) & 1)*8 + (lane & 7);
    const uint32_t bk_   = ((lane >> 3) & 1)*8;
    const int rlo = wid*16 + g, rhi = rlo + 8;

    for (int ph = 0; ph < 3; ph++) {
        const __nv_bfloat16* W = g_wb + ph*65536;
        #pragma unroll
        for (int i = 0; i < 32; i++) {
            int e = tid + i*256;
            int row = e >> 5, c8 = e & 31;
            *(uint4*)&Wt[row*264 + c8*8] = *(const uint4*)&W[row*256 + c8*8];
        }
        __syncthreads();

        float acc[32][4];
        #pragma unroll
        for (int n = 0; n < 32; n++)
            #pragma unroll
            for (int c = 0; c < 4; c++) acc[n][c] = 0.f;

        #pragma unroll
        for (int s = 0; s < 16; s++) {
            uint32_t a[4];
            LDSM4(a, sb + GA + (uint32_t)((arow*264 + s*16 + acol0)*2));
            #pragma unroll
            for (int j2 = 0; j2 < 16; j2++) {
                uint32_t b[4];
                LDSM4(b, sb + (uint32_t)(((j2*16 + brow)*264 + s*16 + bk_)*2));
                mma16816(acc[2*j2],   a, b);
                mma16816(acc[2*j2+1], a, b + 2);
            }
        }
        __syncthreads();                 // W consumed; region becomes stage

        const float* bias = (ph == 0) ? bq : (ph == 1) ? bk : bv;
        float scale = (ph == 0) ? (0.0625f * LOG2E) : 1.f;
        __nv_bfloat16* SD = (__nv_bfloat16*)(sm + GW);
        #pragma unroll
        for (int j2 = 0; j2 < 16; j2++)
            #pragma unroll
            for (int hi = 0; hi < 2; hi++) {
                int o = j2*16 + hi*8 + tig*2;
                float b0 = bias[o], b1 = bias[o+1];
                float* ac = acc[2*j2 + hi];
                __nv_bfloat162 plo = __floats2bfloat162_rn((ac[0]+b0)*scale, (ac[1]+b1)*scale);
                __nv_bfloat162 phi = __floats2bfloat162_rn((ac[2]+b0)*scale, (ac[3]+b1)*scale);
                *(uint32_t*)&SD[rlo*264 + o] = *(uint32_t*)&plo;
                *(uint32_t*)&SD[rhi*264 + o] = *(uint32_t*)&phi;
            }
        __syncthreads();
        __nv_bfloat16* outb = ((ph == 0) ? g_qb : (ph == 1) ? g_kb : g_vb)
                              + (size_t)bb * Nt * Ct;
        #pragma unroll
        for (int i = 0; i < 16; i++) {
            int e = tid + i*256;
            int r = e >> 5, c8 = e & 31;
            *(uint4*)&outb[(size_t)(n0 + r)*Ct + c8*8] = *(uint4*)&SD[r*264 + c8*8];
        }
        __syncthreads();                 // stores drained before next W load
    }
}

// ---------------------------------------------------------------------------
// Output projection + residual (bf16 W), fp32 out [o][n]
// ---------------------------------------------------------------------------
__global__ __launch_bounds__(256, 1) void oproj_gemm(const float* __restrict__ bo,
                                                     const float* __restrict__ xres,
                                                     float* __restrict__ outp) {
    extern __shared__ char sm[];
    __nv_bfloat16* Wt = (__nv_bfloat16*)(sm + GW);
    __nv_bfloat16* At = (__nv_bfloat16*)(sm + GA);
    const uint32_t sb = cvta_smem(sm);
    const int tid = threadIdx.x, lane = tid & 31, wid = tid >> 5;
    const int g = lane >> 2, tig = lane & 3;
    const int n0 = blockIdx.x * 128, bb = blockIdx.y;
    const __nv_bfloat16* A = g_aob + (size_t)bb * Nt * Ct;
    const __nv_bfloat16* W = g_wb + 3*65536;

    #pragma unroll
    for (int i = 0; i < 16; i++) {
        int e = tid + i*256;
        int r = e >> 5, c8 = e & 31;
        *(uint4*)&At[r*264 + c8*8] = *(const uint4*)&A[(size_t)(n0 + r)*Ct + c8*8];
    }
    #pragma unroll
    for (int i = 0; i < 32; i++) {
        int e = tid + i*256;
        int row = e >> 5, c8 = e & 31;
        *(uint4*)&Wt[row*264 + c8*8] = *(const uint4*)&W[row*256 + c8*8];
    }
    __syncthreads();

    float acc[32][4];
    #pragma unroll
    for (int n = 0; n < 32; n++)
        #pragma unroll
        for (int c = 0; c < 4; c++) acc[n][c] = 0.f;

    const uint32_t arow  = wid*16 + (lane & 15);
    const uint32_t acol0 = (lane >> 4) * 8;
    const uint32_t brow  = ((lane >> 4) & 1)*8 + (lane & 7);
    const uint32_t bk_   = ((lane >> 3) & 1)*8;

    #pragma unroll
    for (int s = 0; s < 16; s++) {
        uint32_t a[4];
        LDSM4(a, sb + GA + (uint32_t)((arow*264 + s*16 + acol0)*2));
        #pragma unroll
        for (int j2 = 0; j2 < 16; j2++) {
            uint32_t b[4];
            LDSM4(b, sb + (uint32_t)(((j2*16 + brow)*264 + s*16 + bk_)*2));
            mma16816(acc[2*j2],   a, b);
            mma16816(acc[2*j2+1], a, b + 2);
        }
    }
    __syncthreads();

    const int rlo = wid*16 + g, rhi = rlo + 8;
    float* SD = (float*)(sm + GW);       // [128][132] fp32 per half
    #pragma unroll
    for (int half = 0; half < 2; half++) {
        #pragma unroll
        for (int j2 = half*8; j2 < half*8 + 8; j2++)
            #pragma unroll
            for (int hi = 0; hi < 2; hi++) {
                int o = j2*16 + hi*8 + tig*2;
                int ol = o - half*128;
                float* ac = acc[2*j2 + hi];
                SD[ol*132 + rlo]     = ac[0];
                SD[(ol+1)*132 + rlo] = ac[1];
                SD[ol*132 + rhi]     = ac[2];
                SD[(ol+1)*132 + rhi] = ac[3];
            }
        __syncthreads();
        #pragma unroll
        for (int i = 0; i < 16; i++) {
            int e = tid + i*256;
            int r = e >> 5, c4 = e & 31;
            int o = half*128 + r;
            size_t base = ((size_t)bb*Ct + o)*Nt + n0 + c4*4;
            float4 v  = *(float4*)&SD[r*132 + c4*4];
            float4 xv = *(const float4*)&xres[base];
            float bo_ = bo[o];
            v.x += bo_ + xv.x; v.y += bo_ + xv.y;
            v.z += bo_ + xv.z; v.w += bo_ + xv.w;
            *(float4*)&outp[base] = v;
        }
        __syncthreads();
    }
}

// ---------------------------------------------------------------------------
// Flash attention via mma.sync. Br=128 (8 warps x 16 rows), Bc=64, D=256.
// K and V both [tok][ch] tiles; V fed via ldmatrix.trans. exp2 domain.
// ---------------------------------------------------------------------------
#define QSTR 264
#define KSTR 264
#define VSTR 264
#define SM_K    (128*QSTR*2)             // Q at 0: 67584
#define SM_KBUF (64*KSTR*2)              // 33792
#define SM_V    (SM_K + 2*SM_KBUF)       // 135168
#define SM_VBUF (64*VSTR*2)              // 33792
#define FLASH_SMEM (SM_V + 2*SM_VBUF)    // 202752

__device__ __forceinline__ void issue_kv(uint32_t sb,
                                         const __nv_bfloat16* Kp,
                                         const __nv_bfloat16* Vp,
                                         int kt, int buf, int tid) {
    uint32_t kbase = sb + SM_K + buf*SM_KBUF;
    uint32_t vbase = sb + SM_V + buf*SM_VBUF;
    #pragma unroll
    for (int i = 0; i < 8; i++) {
        int e = tid + i*256;
        int r = e >> 5, c8 = e & 31;
        size_t goff = (size_t)(kt*64 + r)*Ct + c8*8;
        uint32_t soff = (uint32_t)(r*264 + c8*8)*2;
        CP_ASYNC16(kbase + soff, (const void*)&Kp[goff]);
        CP_ASYNC16(vbase + soff, (const void*)&Vp[goff]);
    }
    CP_COMMIT();
}

__global__ __launch_bounds__(256, 1) void flash_mma() {
    extern __shared__ char smem[];
    const uint32_t sb = cvta_smem(smem);
    const int tid = threadIdx.x, lane = tid & 31, wid = tid >> 5;
    const int g = lane >> 2, tig = lane & 3;
    const int n0 = blockIdx.x * 128, bb = blockIdx.y;
    const __nv_bfloat16* Qp = g_qb + (size_t)bb * Nt * Ct;
    const __nv_bfloat16* Kp = g_kb + (size_t)bb * Nt * Ct;
    const __nv_bfloat16* Vp = g_vb + (size_t)bb * Nt * Ct;

    issue_kv(sb, Kp, Vp, 0, 0, tid);

    #pragma unroll
    for (int i = 0; i < 16; i++) {
        int e = tid + i*256;
        int r = e >> 5, c8 = e & 31;
        uint4 u = *(const uint4*)&Qp[(size_t)(n0 + r)*Ct + c8*8];
        *(uint4*)(smem + (size_t)(r*QSTR + c8*8)*2) = u;
    }

    float m0 = -1e30f, m1 = -1e30f, l0 = 0.f, l1 = 0.f;   // l: per-lane partials
    float oAcc[32][4];
    #pragma unroll
    for (int n = 0; n < 32; n++)
        #pragma unroll
        for (int c = 0; c < 4; c++) oAcc[n][c] = 0.f;

    const uint32_t arow  = wid*16 + (lane & 15);
    const uint32_t acol0 = (lane >> 4) * 8;
    const uint32_t btok  = ((lane >> 4) & 1)*8 + (lane & 7);
    const uint32_t bkoff = ((lane >> 3) & 1)*8;
    const uint32_t vtok  = ((lane >> 3) & 1)*8 + (lane & 7);
    const uint32_t vch   = (lane >> 4) * 8;

    for (int kt = 0; kt < 64; kt++) {
        __syncthreads();
        if (kt < 63) { issue_kv(sb, Kp, Vp, kt+1, (kt+1)&1, tid); CP_WAIT(1); }
        else         { CP_WAIT(0); }
        __syncthreads();

        uint32_t kbase = sb + SM_K + (kt&1)*SM_KBUF;
        uint32_t vbase = sb + SM_V + (kt&1)*SM_VBUF;

        // S = Q K^T (scores already in log2 domain via Q pre-scale)
        float sAcc[8][4] = {};
        #pragma unroll
        for (int s = 0; s < 16; s++) {
            uint32_t a[4];
            LDSM4(a, sb + (uint32_t)((arow*QSTR + s*16 + acol0)*2));
            #pragma unroll
            for (int j2 = 0; j2 < 4; j2++) {
                uint32_t b[4];
                LDSM4(b, kbase + (uint32_t)(((j2*16 + btok)*KSTR + s*16 + bkoff)*2));
                mma16816(sAcc[2*j2],   a, b);
                mma16816(sAcc[2*j2+1], a, b + 2);
            }
        }

        float pm0 = -1e30f, pm1 = -1e30f;
        #pragma unroll
        for (int j = 0; j < 8; j++) {
            pm0 = fmaxf(pm0, fmaxf(sAcc[j][0], sAcc[j][1]));
            pm1 = fmaxf(pm1, fmaxf(sAcc[j][2], sAcc[j][3]));
        }
        pm0 = fmaxf(pm0, __shfl_xor_sync(0xffffffffu, pm0, 1));
        pm0 = fmaxf(pm0, __shfl_xor_sync(0xffffffffu, pm0, 2));
        pm1 = fmaxf(pm1, __shfl_xor_sync(0xffffffffu, pm1, 1));
        pm1 = fmaxf(pm1, __shfl_xor_sync(0xffffffffu, pm1, 2));
        float mn0 = fmaxf(m0, pm0), mn1 = fmaxf(m1, pm1);
        float al0 = exp2f(m0 - mn0), al1 = exp2f(m1 - mn1);

        float rs0 = 0.f, rs1 = 0.f;
        uint32_t pfrag[4][4];
        #pragma unroll
        for (int j = 0; j < 8; j++) {
            float p0 = exp2f(sAcc[j][0] - mn0);
            float p1 = exp2f(sAcc[j][1] - mn0);
            float p2 = exp2f(sAcc[j][2] - mn1);
            float p3 = exp2f(sAcc[j][3] - mn1);
            rs0 += p0 + p1; rs1 += p2 + p3;
            __nv_bfloat162 u01 = __floats2bfloat162_rn(p0, p1);
            __nv_bfloat162 u23 = __floats2bfloat162_rn(p2, p3);
            int s = j >> 1, hi = j & 1;
            pfrag[s][hi*2 + 0] = *(uint32_t*)&u01;
            pfrag[s][hi*2 + 1] = *(uint32_t*)&u23;
        }
        l0 = al0*l0 + rs0;                 // per-lane partial; quad-sum deferred
        l1 = al1*l1 + rs1;
        m0 = mn0; m1 = mn1;

        #pragma unroll
        for (int n = 0; n < 32; n++) {
            oAcc[n][0] *= al0; oAcc[n][1] *= al0;
            oAcc[n][2] *= al1; oAcc[n][3] *= al1;
        }

        // O += P V  (V in [tok][ch], trans-ldmatrix for B)
        #pragma unroll
        for (int s = 0; s < 4; s++) {
            #pragma unroll
            for (int n2 = 0; n2 < 16; n2++) {
                uint32_t b[4];
                LDSM4T(b, vbase + (uint32_t)(((s*16 + vtok)*VSTR + n2*16 + vch)*2));
                mma16816(oAcc[2*n2],   pfrag[s], b);
                mma16816(oAcc[2*n2+1], pfrag[s], b + 2);
            }
        }
    }

    // finalize l (quad reduction) and write O/l -> g_aob
    l0 += __shfl_xor_sync(0xffffffffu, l0, 1);
    l0 += __shfl_xor_sync(0xffffffffu, l0, 2);
    l1 += __shfl_xor_sync(0xffffffffu, l1, 1);
    l1 += __shfl_xor_sync(0xffffffffu, l1, 2);
    float inv0 = 1.f / l0, inv1 = 1.f / l1;
    __nv_bfloat16* AO = g_aob + (size_t)bb * Nt * Ct;
    int r0 = n0 + wid*16 + g, r1 = r0 + 8;
    #pragma unroll
    for (int n = 0; n < 32; n++) {
        int ch = n*8 + tig*2;
        __nv_bfloat162 u0 = __floats2bfloat162_rn(oAcc[n][0]*inv0, oAcc[n][1]*inv0);
        __nv_bfloat162 u1 = __floats2bfloat162_rn(oAcc[n][2]*inv1, oAcc[n][3]*inv1);
        *(uint32_t*)&AO[(size_t)r0*Ct + ch] = *(uint32_t*)&u0;
        *(uint32_t*)&AO[(size_t)r1*Ct + ch] = *(uint32_t*)&u1;
    }
}

// ---------------------------------------------------------------------------
extern "C" void kernel_launch(void* const* d_in, const int* in_sizes, int n_in,
                              void* d_out, int out_size) {
    (void)in_sizes; (void)n_in; (void)out_size;
    const float* x   = (const float*)d_in[0];
    const float* gnw = (const float*)d_in[1];
    const float* gnb = (const float*)d_in[2];
    const float* wq  = (const float*)d_in[3];
    const float* bq  = (const float*)d_in[4];
    const float* wk  = (const float*)d_in[5];
    const float* bk  = (const float*)d_in[6];
    const float* wv  = (const float*)d_in[7];
    const float* bv  = (const float*)d_in[8];
    const float* wo  = (const float*)d_in[9];
    const float* bo  = (const float*)d_in[10];
    float* out = (float*)d_out;

    cudaFuncSetAttribute(flash_mma,  cudaFuncAttributeMaxDynamicSharedMemorySize, FLASH_SMEM);
    cudaFuncSetAttribute(qkv_gemm,   cudaFuncAttributeMaxDynamicSharedMemorySize, QKV_SMEM);
    cudaFuncSetAttribute(oproj_gemm, cudaFuncAttributeMaxDynamicSharedMemorySize, QKV_SMEM);

    wcvt<<<256, 256>>>(wq, wk, wv, wo);
    gn_kernel<<<256, 256>>>(x, gnw, gnb);

    dim3 gg(Nt/128, Bt);
    qkv_gemm<<<gg, 256, QKV_SMEM>>>(bq, bk, bv);
    flash_mma<<<gg, 256, FLASH_SMEM>>>();
    oproj_gemm<<<gg, 256, QKV_SMEM>>>(bo, x, out);
}